// round 3
// baseline (speedup 1.0000x reference)
#include <cuda_runtime.h>
#include <cstdint>

#define B_  4
#define N_  2048
#define C_  1024
#define H_  16
#define HD_ 64
#define BH_ (B_*H_)

// Scratch (static device globals: allocation-free)
__device__ float g_q [BH_ * N_ * HD_];
__device__ float g_k [BH_ * N_ * HD_];
__device__ float g_v [BH_ * N_ * HD_];
__device__ float g_ao[(size_t)B_ * N_ * C_];

__device__ __forceinline__ float to_tf32(float x) {
    uint32_t y;
    asm("cvt.rna.tf32.f32 %0, %1;" : "=r"(y) : "f"(x));
    return __uint_as_float(y);
}

__device__ __forceinline__ void mma_tf32(float* c, const float* a, const float* b) {
    asm volatile(
        "mma.sync.aligned.m16n8k8.row.col.f32.tf32.tf32.f32 "
        "{%0,%1,%2,%3}, {%4,%5,%6,%7}, {%8,%9}, {%0,%1,%2,%3};"
        : "+f"(c[0]), "+f"(c[1]), "+f"(c[2]), "+f"(c[3])
        : "r"(__float_as_uint(a[0])), "r"(__float_as_uint(a[1])),
          "r"(__float_as_uint(a[2])), "r"(__float_as_uint(a[3])),
          "r"(__float_as_uint(b[0])), "r"(__float_as_uint(b[1])));
}

// FFMA-only 2^x (avoids MUFU.EX2 throughput wall). x <= 0 expected; clamped.
__device__ __forceinline__ float fexp2(float x) {
    x = fmaxf(x, -125.0f);
    float z  = x + 12582912.0f;      // 1.5*2^23: round-to-nearest-int trick
    float fi = z - 12582912.0f;
    float f  = x - fi;               // f in [-0.5, 0.5]
    int   i  = __float_as_int(z) - 0x4B400000;
    float p  = 1.3333558e-3f;
    p = fmaf(p, f, 9.6181291e-3f);
    p = fmaf(p, f, 5.5504109e-2f);
    p = fmaf(p, f, 2.4022651e-1f);
    p = fmaf(p, f, 6.9314718e-1f);
    p = fmaf(p, f, 1.0f);
    return __int_as_float((i + 127) << 23) * p;
}

#define LOG2E 1.4426950408889634f

// ============================================================================
// TF32 GEMM: C[M,Nd] = A[M,K] @ W[Nd,K]^T  (both row-major, K contiguous)
// MODE 1: A = x, Nd=3072, epilogue = RoPE + scatter to g_q/g_k/g_v
// MODE 0: A = g_ao, Nd=1024, epilogue = +bias -> out
// Block tile 128x128x32, 256 threads, warp tile 32x64, double-buffered smem.
// ============================================================================
#define GEMM_LDA 132
#define GEMM_SMEM (2 * 2 * 32 * GEMM_LDA * 4)   // As + Bs, 2 buffers each

template<int MODE>
__global__ void gemm_tf32_kernel(const float* __restrict__ A,
                                 const float* __restrict__ W,
                                 const float* __restrict__ bias,
                                 const float* __restrict__ cosT,
                                 const float* __restrict__ sinT,
                                 float* __restrict__ out, int Nd)
{
    const int K = C_;
    extern __shared__ float sm[];
    float* As = sm;
    float* Bs = sm + 2 * 32 * GEMM_LDA;

    const int tid  = threadIdx.x;
    const int wid  = tid >> 5;
    const int lane = tid & 31;
    const int warpM = (wid & 3) * 32;
    const int warpN = (wid >> 2) * 64;
    const int rowBase = blockIdx.y * 128;
    const int colBase = blockIdx.x * 128;

    const float* Ap = (MODE == 1) ? A : g_ao;

    float acc[2][8][4];
#pragma unroll
    for (int mt = 0; mt < 2; mt++)
#pragma unroll
        for (int nt = 0; nt < 8; nt++)
#pragma unroll
            for (int i = 0; i < 4; i++) acc[mt][nt][i] = 0.f;

    float4 ar[4], br[4];

    // ---- load tile t from global into registers ----
#define LOADG(t)                                                              \
    {                                                                         \
        _Pragma("unroll")                                                     \
        for (int i = 0; i < 4; i++) {                                         \
            int idx = tid + i * 256;                                          \
            int m = idx >> 3, kq = idx & 7;                                   \
            ar[i] = *(const float4*)&Ap[(size_t)(rowBase + m) * K + (t) * 32 + kq * 4]; \
            br[i] = *(const float4*)&W [(size_t)(colBase + m) * K + (t) * 32 + kq * 4]; \
        }                                                                     \
    }

    // ---- store registers into smem buffer (transposed, tf32) ----
#define STORES(buf)                                                           \
    {                                                                         \
        _Pragma("unroll")                                                     \
        for (int i = 0; i < 4; i++) {                                         \
            int idx = tid + i * 256;                                          \
            int m = idx >> 3, kq = idx & 7;                                   \
            float* a4 = &As[((buf) * 32 + kq * 4) * GEMM_LDA + m];            \
            a4[0 * GEMM_LDA] = to_tf32(ar[i].x);                              \
            a4[1 * GEMM_LDA] = to_tf32(ar[i].y);                              \
            a4[2 * GEMM_LDA] = to_tf32(ar[i].z);                              \
            a4[3 * GEMM_LDA] = to_tf32(ar[i].w);                              \
            float* b4 = &Bs[((buf) * 32 + kq * 4) * GEMM_LDA + m];            \
            b4[0 * GEMM_LDA] = to_tf32(br[i].x);                              \
            b4[1 * GEMM_LDA] = to_tf32(br[i].y);                              \
            b4[2 * GEMM_LDA] = to_tf32(br[i].z);                              \
            b4[3 * GEMM_LDA] = to_tf32(br[i].w);                              \
        }                                                                     \
    }

    LOADG(0);
    STORES(0);
    __syncthreads();

    const int NT = K / 32;   // 32
    for (int t = 0; t < NT; t++) {
        if (t + 1 < NT) LOADG(t + 1);

        const int buf = t & 1;
#pragma unroll
        for (int kk = 0; kk < 4; kk++) {
            const int k0 = buf * 32 + kk * 8;
            const int kc = k0 + (lane & 3);
            float af[2][4], bf[8][2];
#pragma unroll
            for (int mt = 0; mt < 2; mt++) {
                int r = warpM + mt * 16 + (lane >> 2);
                af[mt][0] = As[kc * GEMM_LDA + r];
                af[mt][1] = As[kc * GEMM_LDA + r + 8];
                af[mt][2] = As[(kc + 4) * GEMM_LDA + r];
                af[mt][3] = As[(kc + 4) * GEMM_LDA + r + 8];
            }
#pragma unroll
            for (int nt = 0; nt < 8; nt++) {
                int n = warpN + nt * 8 + (lane >> 2);
                bf[nt][0] = Bs[kc * GEMM_LDA + n];
                bf[nt][1] = Bs[(kc + 4) * GEMM_LDA + n];
            }
#pragma unroll
            for (int mt = 0; mt < 2; mt++)
#pragma unroll
                for (int nt = 0; nt < 8; nt++)
                    mma_tf32(acc[mt][nt], af[mt], bf[nt]);
        }

        if (t + 1 < NT) {
            STORES((t + 1) & 1);
            __syncthreads();
        }
    }

    // ---- epilogue ----
    if (MODE == 0) {
#pragma unroll
        for (int mt = 0; mt < 2; mt++)
#pragma unroll
            for (int nt = 0; nt < 8; nt++) {
                int r = rowBase + warpM + mt * 16 + (lane >> 2);
                int c = colBase + warpN + nt * 8 + (lane & 3) * 2;
                float b0 = bias[c], b1 = bias[c + 1];
                out[(size_t)r * Nd + c]           = acc[mt][nt][0] + b0;
                out[(size_t)r * Nd + c + 1]       = acc[mt][nt][1] + b1;
                out[(size_t)(r + 8) * Nd + c]     = acc[mt][nt][2] + b0;
                out[(size_t)(r + 8) * Nd + c + 1] = acc[mt][nt][3] + b1;
            }
    } else {
        // warp covers exactly one head (64 cols). slot: 0-15 q, 16-31 k, 32-47 v
        const int slot = (colBase + warpN) >> 6;
        const int type = slot >> 4;
        const int h    = slot & 15;
        float* dst = (type == 0) ? g_q : (type == 1 ? g_k : g_v);
#pragma unroll
        for (int mt = 0; mt < 2; mt++)
#pragma unroll
            for (int nt = 0; nt < 4; nt++) {
                int rA  = rowBase + warpM + mt * 16 + (lane >> 2);
                int hdb = nt * 8 + (lane & 3) * 2;
#pragma unroll
                for (int i = 0; i < 4; i++) {
                    int rr = rA + ((i & 2) ? 8 : 0);
                    int hd = hdb + (i & 1);
                    int n  = rr & (N_ - 1);
                    int b  = rr >> 11;
                    float lo = acc[mt][nt][i];
                    float hi = acc[mt][nt + 4][i];
                    float oL, oH;
                    if (type < 2) {
                        float cL = cosT[n * HD_ + hd],      sL = sinT[n * HD_ + hd];
                        float cH = cosT[n * HD_ + hd + 32], sH = sinT[n * HD_ + hd + 32];
                        oL = lo * cL - hi * sL;
                        oH = hi * cH + lo * sH;
                    } else {
                        oL = lo; oH = hi;
                    }
                    size_t base = ((size_t)(b * H_ + h) * N_ + n) * HD_;
                    dst[base + hd]      = oL;
                    dst[base + hd + 32] = oH;
                }
            }
    }
#undef LOADG
#undef STORES
}

// ============================================================================
// Flash attention: per block = one (b,h) x one 64-row Q tile, 128 threads.
// Online softmax (fp32), QK^T and PV via tf32 mma. Scale folded into Q.
// ============================================================================
#define ATTN_LD 68
#define ATTN_SMEM (3 * 64 * ATTN_LD * 4)

__global__ void attn_kernel()
{
    extern __shared__ float sm[];
    float* Ks = sm;
    float* Vs = sm + 64 * ATTN_LD;
    float* Ps = sm + 128 * ATTN_LD;   // also Q staging

    const int tid = threadIdx.x, wid = tid >> 5, lane = tid & 31;
    const int bh  = blockIdx.y;
    const int b   = bh >> 4, h = bh & 15;
    const int q0  = blockIdx.x * 64;

    const float* Qp = g_q + (size_t)bh * N_ * HD_;
    const float* Kp = g_k + (size_t)bh * N_ * HD_;
    const float* Vp = g_v + (size_t)bh * N_ * HD_;

    // stage Q (pre-scaled by hd^-0.5 = 0.125, exact in tf32)
#pragma unroll
    for (int i = 0; i < 8; i++) {
        int idx = tid + i * 128;
        int r = idx >> 4, c4 = idx & 15;
        float4 v = *(const float4*)&Qp[(size_t)(q0 + r) * HD_ + c4 * 4];
        float* p = &Ps[r * ATTN_LD + c4 * 4];
        p[0] = to_tf32(v.x * 0.125f);
        p[1] = to_tf32(v.y * 0.125f);
        p[2] = to_tf32(v.z * 0.125f);
        p[3] = to_tf32(v.w * 0.125f);
    }
    __syncthreads();

    float qa[8][4];
    {
        int r = wid * 16 + (lane >> 2);
#pragma unroll
        for (int kk = 0; kk < 8; kk++) {
            int kc = kk * 8 + (lane & 3);
            qa[kk][0] = Ps[r * ATTN_LD + kc];
            qa[kk][1] = Ps[(r + 8) * ATTN_LD + kc];
            qa[kk][2] = Ps[r * ATTN_LD + kc + 4];
            qa[kk][3] = Ps[(r + 8) * ATTN_LD + kc + 4];
        }
    }

    float o[8][4];
#pragma unroll
    for (int nt = 0; nt < 8; nt++)
#pragma unroll
        for (int i = 0; i < 4; i++) o[nt][i] = 0.f;
    float m0 = -1e30f, m1 = -1e30f, l0 = 0.f, l1 = 0.f;
    float* Pw = Ps + wid * 16 * ATTN_LD;

    for (int kt = 0; kt < N_ / 64; kt++) {
        __syncthreads();   // protect Ks/Vs from previous iteration readers
#pragma unroll
        for (int i = 0; i < 8; i++) {
            int idx = tid + i * 128;
            int r = idx >> 4, c4 = idx & 15;
            float4 kv = *(const float4*)&Kp[(size_t)(kt * 64 + r) * HD_ + c4 * 4];
            float* pk = &Ks[r * ATTN_LD + c4 * 4];
            pk[0] = to_tf32(kv.x); pk[1] = to_tf32(kv.y);
            pk[2] = to_tf32(kv.z); pk[3] = to_tf32(kv.w);
            float4 vv = *(const float4*)&Vp[(size_t)(kt * 64 + r) * HD_ + c4 * 4];
            float* pv = &Vs[r * ATTN_LD + c4 * 4];
            pv[0] = to_tf32(vv.x); pv[1] = to_tf32(vv.y);
            pv[2] = to_tf32(vv.z); pv[3] = to_tf32(vv.w);
        }
        __syncthreads();

        // S = Qs @ Ks^T  (warp: 16 q-rows x 64 keys)
        float s[8][4];
#pragma unroll
        for (int nt = 0; nt < 8; nt++)
#pragma unroll
            for (int i = 0; i < 4; i++) s[nt][i] = 0.f;
#pragma unroll
        for (int kk = 0; kk < 8; kk++) {
            int kc = kk * 8 + (lane & 3);
            float bf[8][2];
#pragma unroll
            for (int nt = 0; nt < 8; nt++) {
                int nn = nt * 8 + (lane >> 2);
                bf[nt][0] = Ks[nn * ATTN_LD + kc];
                bf[nt][1] = Ks[nn * ATTN_LD + kc + 4];
            }
#pragma unroll
            for (int nt = 0; nt < 8; nt++)
                mma_tf32(s[nt], qa[kk], bf[nt]);
        }

        // online softmax (rows lane>>2 and lane>>2 + 8)
        float mx0 = -1e30f, mx1 = -1e30f;
#pragma unroll
        for (int nt = 0; nt < 8; nt++) {
            mx0 = fmaxf(mx0, fmaxf(s[nt][0], s[nt][1]));
            mx1 = fmaxf(mx1, fmaxf(s[nt][2], s[nt][3]));
        }
        mx0 = fmaxf(mx0, __shfl_xor_sync(0xffffffffu, mx0, 1));
        mx0 = fmaxf(mx0, __shfl_xor_sync(0xffffffffu, mx0, 2));
        mx1 = fmaxf(mx1, __shfl_xor_sync(0xffffffffu, mx1, 1));
        mx1 = fmaxf(mx1, __shfl_xor_sync(0xffffffffu, mx1, 2));
        float mn0 = fmaxf(m0, mx0), mn1 = fmaxf(m1, mx1);
        float c0 = fexp2((m0 - mn0) * LOG2E);
        float c1 = fexp2((m1 - mn1) * LOG2E);

        float rs0 = 0.f, rs1 = 0.f;
#pragma unroll
        for (int nt = 0; nt < 8; nt++) {
            s[nt][0] = fexp2((s[nt][0] - mn0) * LOG2E); rs0 += s[nt][0];
            s[nt][1] = fexp2((s[nt][1] - mn0) * LOG2E); rs0 += s[nt][1];
            s[nt][2] = fexp2((s[nt][2] - mn1) * LOG2E); rs1 += s[nt][2];
            s[nt][3] = fexp2((s[nt][3] - mn1) * LOG2E); rs1 += s[nt][3];
        }
        rs0 += __shfl_xor_sync(0xffffffffu, rs0, 1);
        rs0 += __shfl_xor_sync(0xffffffffu, rs0, 2);
        rs1 += __shfl_xor_sync(0xffffffffu, rs1, 1);
        rs1 += __shfl_xor_sync(0xffffffffu, rs1, 2);

        m0 = mn0; m1 = mn1;
        l0 = l0 * c0 + rs0;
        l1 = l1 * c1 + rs1;
#pragma unroll
        for (int nt = 0; nt < 8; nt++) {
            o[nt][0] *= c0; o[nt][1] *= c0;
            o[nt][2] *= c1; o[nt][3] *= c1;
        }

        // store P (tf32) into per-warp smem region
        {
            int r = lane >> 2, cb = (lane & 3) * 2;
#pragma unroll
            for (int nt = 0; nt < 8; nt++) {
                Pw[r * ATTN_LD + nt * 8 + cb]           = to_tf32(s[nt][0]);
                Pw[r * ATTN_LD + nt * 8 + cb + 1]       = to_tf32(s[nt][1]);
                Pw[(r + 8) * ATTN_LD + nt * 8 + cb]     = to_tf32(s[nt][2]);
                Pw[(r + 8) * ATTN_LD + nt * 8 + cb + 1] = to_tf32(s[nt][3]);
            }
        }
        __syncwarp();

        // O += P @ V
#pragma unroll
        for (int kk = 0; kk < 8; kk++) {
            int kc = kk * 8 + (lane & 3);
            float pa[4];
            pa[0] = Pw[(lane >> 2) * ATTN_LD + kc];
            pa[1] = Pw[((lane >> 2) + 8) * ATTN_LD + kc];
            pa[2] = Pw[(lane >> 2) * ATTN_LD + kc + 4];
            pa[3] = Pw[((lane >> 2) + 8) * ATTN_LD + kc + 4];
#pragma unroll
            for (int nt = 0; nt < 8; nt++) {
                float bf[2];
                bf[0] = Vs[kc * ATTN_LD + nt * 8 + (lane >> 2)];
                bf[1] = Vs[(kc + 4) * ATTN_LD + nt * 8 + (lane >> 2)];
                mma_tf32(o[nt], pa, bf);
            }
        }
        __syncwarp();
    }

    // epilogue: normalize and write to g_ao in [B,N,C] layout
    float i0 = 1.f / l0, i1 = 1.f / l1;
    int r = q0 + wid * 16 + (lane >> 2);
    size_t rowA = ((size_t)b * N_ + r) * C_ + h * HD_;
    size_t rowB = ((size_t)b * N_ + r + 8) * C_ + h * HD_;
#pragma unroll
    for (int nt = 0; nt < 8; nt++) {
        int d = nt * 8 + (lane & 3) * 2;
        g_ao[rowA + d]     = o[nt][0] * i0;
        g_ao[rowA + d + 1] = o[nt][1] * i0;
        g_ao[rowB + d]     = o[nt][2] * i1;
        g_ao[rowB + d + 1] = o[nt][3] * i1;
    }
}

// ============================================================================
extern "C" void kernel_launch(void* const* d_in, const int* in_sizes, int n_in,
                              void* d_out, int out_size)
{
    const float* x     = (const float*)d_in[0];
    const float* cosT  = (const float*)d_in[1];
    const float* sinT  = (const float*)d_in[2];
    const float* Wqkv  = (const float*)d_in[3];
    const float* Wproj = (const float*)d_in[4];
    const float* bproj = (const float*)d_in[5];
    float* out = (float*)d_out;

    cudaFuncSetAttribute(gemm_tf32_kernel<1>,
                         cudaFuncAttributeMaxDynamicSharedMemorySize, GEMM_SMEM);
    cudaFuncSetAttribute(gemm_tf32_kernel<0>,
                         cudaFuncAttributeMaxDynamicSharedMemorySize, GEMM_SMEM);
    cudaFuncSetAttribute(attn_kernel,
                         cudaFuncAttributeMaxDynamicSharedMemorySize, ATTN_SMEM);

    // 1) QKV GEMM + RoPE -> g_q/g_k/g_v  (M=8192, Nd=3072, K=1024)
    dim3 g1(3 * C_ / 128, (B_ * N_) / 128);
    gemm_tf32_kernel<1><<<g1, 256, GEMM_SMEM>>>(x, Wqkv, nullptr, cosT, sinT,
                                                nullptr, 3 * C_);

    // 2) flash attention -> g_ao
    dim3 g2(N_ / 64, BH_);
    attn_kernel<<<g2, 128, ATTN_SMEM>>>();

    // 3) out proj + bias -> out  (M=8192, Nd=1024, K=1024)
    dim3 g3(C_ / 128, (B_ * N_) / 128);
    gemm_tf32_kernel<0><<<g3, 256, GEMM_SMEM>>>(nullptr, Wproj, bproj, nullptr,
                                                nullptr, out, C_);
}

// round 6
// speedup vs baseline: 1.4442x; 1.4442x over previous
#include <cuda_runtime.h>
#include <cstdint>

#define B_  4
#define N_  2048
#define C_  1024
#define H_  16
#define HD_ 64
#define BH_ (B_*H_)

// Scratch (static device globals: allocation-free)
__device__ float g_q [BH_ * N_ * HD_];
__device__ float g_k [BH_ * N_ * HD_];
__device__ float g_v [BH_ * N_ * HD_];
__device__ float g_ao[(size_t)B_ * N_ * C_];

__device__ __forceinline__ uint32_t smem_u32(const void* p) {
    uint32_t a;
    asm("{ .reg .u64 t; cvta.to.shared.u64 t, %1; cvt.u32.u64 %0, t; }"
        : "=r"(a) : "l"(p));
    return a;
}

__device__ __forceinline__ float to_tf32(float x) {
    uint32_t y;
    asm("cvt.rna.tf32.f32 %0, %1;" : "=r"(y) : "f"(x));
    return __uint_as_float(y);
}

__device__ __forceinline__ void mma_tf32(float* c, const float* a, const float* b) {
    asm volatile(
        "mma.sync.aligned.m16n8k8.row.col.f32.tf32.tf32.f32 "
        "{%0,%1,%2,%3}, {%4,%5,%6,%7}, {%8,%9}, {%0,%1,%2,%3};"
        : "+f"(c[0]), "+f"(c[1]), "+f"(c[2]), "+f"(c[3])
        : "r"(__float_as_uint(a[0])), "r"(__float_as_uint(a[1])),
          "r"(__float_as_uint(a[2])), "r"(__float_as_uint(a[3])),
          "r"(__float_as_uint(b[0])), "r"(__float_as_uint(b[1])));
}

// FFMA-only 2^x (avoids MUFU.EX2 throughput wall).
__device__ __forceinline__ float fexp2(float x) {
    x = fmaxf(x, -125.0f);
    float z  = x + 12582912.0f;
    float fi = z - 12582912.0f;
    float f  = x - fi;
    int   i  = __float_as_int(z) - 0x4B400000;
    float p  = 1.3333558e-3f;
    p = fmaf(p, f, 9.6181291e-3f);
    p = fmaf(p, f, 5.5504109e-2f);
    p = fmaf(p, f, 2.4022651e-1f);
    p = fmaf(p, f, 6.9314718e-1f);
    p = fmaf(p, f, 1.0f);
    return __int_as_float((i + 127) << 23) * p;
}

#define LOG2E 1.4426950408889634f

#define CP16(dst, src) \
    asm volatile("cp.async.cg.shared.global [%0], [%1], 16;" \
        :: "r"(dst), "l"(src))
#define CP_COMMIT() asm volatile("cp.async.commit_group;" ::: "memory")
#define CP_WAIT1()  asm volatile("cp.async.wait_group 1;" ::: "memory")
#define CP_WAIT0()  asm volatile("cp.async.wait_group 0;" ::: "memory")

// ============================================================================
// TF32 GEMM: C[M,Nd] = A[M,K] @ W[Nd,K]^T, K=1024.
// Block 128x256, 8 warps (2x4), warp tile 64x64 (mt=4, nt=8), K-chunk 32.
// cp.async raw fp32 -> smem (double buffered); cvt.rna at fragment load.
// MODE 1: A = x, epilogue = RoPE + scatter to g_q/g_k/g_v
// MODE 0: A = g_ao, epilogue = +bias -> out
// ============================================================================
#define GLDA 36                    // floats per row (32 + 4 pad) - conflict free
#define G_ABUF (128*GLDA)          // 4608 floats
#define G_BBUF (256*GLDA)          // 9216 floats
#define GEMM_SMEM_BYTES ((2*G_ABUF + 2*G_BBUF)*4)   // 110592

template<int MODE>
__global__ void __launch_bounds__(256, 1)
gemm_tc(const float* __restrict__ A_, const float* __restrict__ W,
        const float* __restrict__ bias,
        const float* __restrict__ cosT, const float* __restrict__ sinT,
        float* __restrict__ out)
{
    extern __shared__ float smf[];
    const uint32_t sb = smem_u32(smf);
    const int tid = threadIdx.x, wid = tid >> 5, lane = tid & 31;
    const int c0 = lane & 3, r0 = lane >> 2;
    const int warpM = (wid & 1) * 64, warpN = (wid >> 1) * 64;
    const int rowBase = blockIdx.y * 128, colBase = blockIdx.x * 256;
    const float* Ap = (MODE == 1) ? A_ : g_ao;

    float acc[4][8][4];
#pragma unroll
    for (int mt = 0; mt < 4; mt++)
#pragma unroll
        for (int nt = 0; nt < 8; nt++)
#pragma unroll
            for (int i = 0; i < 4; i++) acc[mt][nt][i] = 0.f;

#define GCP(t, buf) {                                                          \
    _Pragma("unroll")                                                          \
    for (int i = 0; i < 4; i++) {                                              \
        int idx = tid + i * 256, m = idx >> 3, q = idx & 7;                    \
        CP16(sb + (uint32_t)((buf) * (G_ABUF*4) + m * (GLDA*4) + q * 16),      \
             (const void*)&Ap[(size_t)(rowBase + m) * C_ + (t) * 32 + q * 4]); \
    }                                                                          \
    _Pragma("unroll")                                                          \
    for (int i = 0; i < 8; i++) {                                              \
        int idx = tid + i * 256, n = idx >> 3, q = idx & 7;                    \
        CP16(sb + (uint32_t)(2*(G_ABUF*4) + (buf) * (G_BBUF*4) +               \
                             n * (GLDA*4) + q * 16),                           \
             (const void*)&W[(size_t)(colBase + n) * C_ + (t) * 32 + q * 4]);  \
    }                                                                          \
    CP_COMMIT(); }

    GCP(0, 0);
    const int NT = C_ / 32;
    for (int t = 0; t < NT; t++) {
        const int buf = t & 1;
        if (t + 1 < NT) { GCP(t + 1, buf ^ 1); CP_WAIT1(); }
        else           { CP_WAIT0(); }
        __syncthreads();
        const float* As_f = smf + buf * G_ABUF;
        const float* Bs_f = smf + 2 * G_ABUF + buf * G_BBUF;
#pragma unroll
        for (int kk = 0; kk < 4; kk++) {
            const int kc = kk * 8 + c0;
            float af[4][4], bf[8][2];
#pragma unroll
            for (int mt = 0; mt < 4; mt++) {
                int r = warpM + mt * 16 + r0;
                af[mt][0] = to_tf32(As_f[r * GLDA + kc]);
                af[mt][1] = to_tf32(As_f[(r + 8) * GLDA + kc]);
                af[mt][2] = to_tf32(As_f[r * GLDA + kc + 4]);
                af[mt][3] = to_tf32(As_f[(r + 8) * GLDA + kc + 4]);
            }
#pragma unroll
            for (int nt = 0; nt < 8; nt++) {
                int n = warpN + nt * 8 + r0;
                bf[nt][0] = to_tf32(Bs_f[n * GLDA + kc]);
                bf[nt][1] = to_tf32(Bs_f[n * GLDA + kc + 4]);
            }
#pragma unroll
            for (int mt = 0; mt < 4; mt++)
#pragma unroll
                for (int nt = 0; nt < 8; nt++)
                    mma_tf32(acc[mt][nt], af[mt], bf[nt]);
        }
        __syncthreads();
    }
#undef GCP

    // ---------------- epilogue ----------------
    if (MODE == 1) {
        // warp covers one head slot (warpN 64-aligned): 0-15 q, 16-31 k, 32-47 v
        const int slot = (colBase + warpN) >> 6;
        const int type = slot >> 4, h = slot & 15;
        float* dst = (type == 0) ? g_q : ((type == 1) ? g_k : g_v);
#pragma unroll
        for (int mt = 0; mt < 4; mt++) {
#pragma unroll
            for (int rs = 0; rs < 2; rs++) {
                int rr = rowBase + warpM + mt * 16 + r0 + rs * 8;
                int n = rr & (N_ - 1), b = rr >> 11;
                size_t base = ((size_t)(b * H_ + h) * N_ + n) * HD_;
#pragma unroll
                for (int nt = 0; nt < 4; nt++) {
#pragma unroll
                    for (int j = 0; j < 2; j++) {
                        int hd = nt * 8 + c0 * 2 + j;
                        float lo = acc[mt][nt][rs * 2 + j];
                        float hi = acc[mt][nt + 4][rs * 2 + j];
                        if (type < 2) {   // RoPE (cos[hd+32]==cos[hd])
                            float cv = cosT[n * HD_ + hd];
                            float sv = sinT[n * HD_ + hd];
                            float t1 = lo * cv - hi * sv;
                            hi = hi * cv + lo * sv;
                            lo = t1;
                        }
                        dst[base + hd]      = lo;
                        dst[base + hd + 32] = hi;
                    }
                }
            }
        }
    } else {
#pragma unroll
        for (int mt = 0; mt < 4; mt++)
#pragma unroll
            for (int nt = 0; nt < 8; nt++) {
                int r = rowBase + warpM + mt * 16 + r0;
                int c = colBase + warpN + nt * 8 + c0 * 2;
                float b0 = bias[c], b1 = bias[c + 1];
                out[(size_t)r * C_ + c]           = acc[mt][nt][0] + b0;
                out[(size_t)r * C_ + c + 1]       = acc[mt][nt][1] + b1;
                out[(size_t)(r + 8) * C_ + c]     = acc[mt][nt][2] + b0;
                out[(size_t)(r + 8) * C_ + c + 1] = acc[mt][nt][3] + b1;
            }
    }
}

// ============================================================================
// Flash attention: block = one (b,h) x 128 q-rows, 4 warps, warp tile 32x64.
// Q resident in smem (ld 68), K (68) / V (72) staged per kt, P smem (68).
// All fragment LDS conflict-free. Online softmax in fp32, FFMA-only exp.
// ============================================================================
#define AQ_OFF 0          // 128*68 = 8704
#define AK_OFF 8704       // 64*68  = 4352
#define AV_OFF 13056      // 64*72  = 4608
#define AP_OFF 17664      // 128*68 = 8704
#define ATTN_SMEM_BYTES (26368 * 4)   // 105472

__global__ void __launch_bounds__(128, 2) attn_kernel()
{
    extern __shared__ float sm[];
    float* Qs = sm + AQ_OFF;
    float* Ks = sm + AK_OFF;
    float* Vs = sm + AV_OFF;
    float* Ps = sm + AP_OFF;

    const int tid = threadIdx.x, wid = tid >> 5, lane = tid & 31;
    const int c0 = lane & 3, r0 = lane >> 2;
    const int warpQ = wid * 32;
    const int bh = blockIdx.y, b = bh >> 4, h = bh & 15;
    const int q0 = blockIdx.x * 128;

    const float* Qp = g_q + (size_t)bh * N_ * HD_;
    const float* Kp = g_k + (size_t)bh * N_ * HD_;
    const float* Vp = g_v + (size_t)bh * N_ * HD_;

    // stage Q (pre-scaled by hd^-0.5 = 0.125, exact in tf32)
#pragma unroll
    for (int i = 0; i < 16; i++) {
        int idx = tid + i * 128, r = idx >> 4, q = idx & 15;
        float4 v = *(const float4*)&Qp[(size_t)(q0 + r) * HD_ + q * 4];
        float* p = &Qs[r * 68 + q * 4];
        p[0] = to_tf32(v.x * 0.125f);
        p[1] = to_tf32(v.y * 0.125f);
        p[2] = to_tf32(v.z * 0.125f);
        p[3] = to_tf32(v.w * 0.125f);
    }

    float o[2][8][4];
#pragma unroll
    for (int mt = 0; mt < 2; mt++)
#pragma unroll
        for (int nt = 0; nt < 8; nt++)
#pragma unroll
            for (int i = 0; i < 4; i++) o[mt][nt][i] = 0.f;
    float mrow[2][2] = {{-1e30f, -1e30f}, {-1e30f, -1e30f}};
    float lrow[2][2] = {{0.f, 0.f}, {0.f, 0.f}};

    for (int kt = 0; kt < N_ / 64; kt++) {
        __syncthreads();   // prior iteration readers done (covers Q stage at kt=0)
#pragma unroll
        for (int i = 0; i < 8; i++) {
            int idx = tid + i * 128, r = idx >> 4, q = idx & 15;
            float4 kv = *(const float4*)&Kp[(size_t)(kt * 64 + r) * HD_ + q * 4];
            float* pk = &Ks[r * 68 + q * 4];
            pk[0] = to_tf32(kv.x); pk[1] = to_tf32(kv.y);
            pk[2] = to_tf32(kv.z); pk[3] = to_tf32(kv.w);
            float4 vv = *(const float4*)&Vp[(size_t)(kt * 64 + r) * HD_ + q * 4];
            float* pv = &Vs[r * 72 + q * 4];
            pv[0] = to_tf32(vv.x); pv[1] = to_tf32(vv.y);
            pv[2] = to_tf32(vv.z); pv[3] = to_tf32(vv.w);
        }
        __syncthreads();

        // S = Q @ K^T   (warp: 32 q-rows x 64 keys)
        float s[2][8][4];
#pragma unroll
        for (int mt = 0; mt < 2; mt++)
#pragma unroll
            for (int nt = 0; nt < 8; nt++)
#pragma unroll
                for (int i = 0; i < 4; i++) s[mt][nt][i] = 0.f;
#pragma unroll
        for (int kk = 0; kk < 8; kk++) {
            int kc = kk * 8 + c0;
            float bf[8][2];
#pragma unroll
            for (int nt = 0; nt < 8; nt++) {
                int nn = nt * 8 + r0;
                bf[nt][0] = Ks[nn * 68 + kc];
                bf[nt][1] = Ks[nn * 68 + kc + 4];
            }
            float af[2][4];
#pragma unroll
            for (int mt = 0; mt < 2; mt++) {
                int r = warpQ + mt * 16 + r0;
                af[mt][0] = Qs[r * 68 + kc];
                af[mt][1] = Qs[(r + 8) * 68 + kc];
                af[mt][2] = Qs[r * 68 + kc + 4];
                af[mt][3] = Qs[(r + 8) * 68 + kc + 4];
            }
#pragma unroll
            for (int mt = 0; mt < 2; mt++)
#pragma unroll
                for (int nt = 0; nt < 8; nt++)
                    mma_tf32(s[mt][nt], af[mt], bf[nt]);
        }

        // online softmax per mt (rows r0 and r0+8)
#pragma unroll
        for (int mt = 0; mt < 2; mt++) {
            float mxA = -1e30f, mxB = -1e30f;
#pragma unroll
            for (int nt = 0; nt < 8; nt++) {
                mxA = fmaxf(mxA, fmaxf(s[mt][nt][0], s[mt][nt][1]));
                mxB = fmaxf(mxB, fmaxf(s[mt][nt][2], s[mt][nt][3]));
            }
            mxA = fmaxf(mxA, __shfl_xor_sync(0xffffffffu, mxA, 1));
            mxA = fmaxf(mxA, __shfl_xor_sync(0xffffffffu, mxA, 2));
            mxB = fmaxf(mxB, __shfl_xor_sync(0xffffffffu, mxB, 1));
            mxB = fmaxf(mxB, __shfl_xor_sync(0xffffffffu, mxB, 2));
            float mnA = fmaxf(mrow[mt][0], mxA);
            float mnB = fmaxf(mrow[mt][1], mxB);
            float cA = fexp2((mrow[mt][0] - mnA) * LOG2E);
            float cB = fexp2((mrow[mt][1] - mnB) * LOG2E);
            float rsA = 0.f, rsB = 0.f;
#pragma unroll
            for (int nt = 0; nt < 8; nt++) {
                s[mt][nt][0] = fexp2((s[mt][nt][0] - mnA) * LOG2E); rsA += s[mt][nt][0];
                s[mt][nt][1] = fexp2((s[mt][nt][1] - mnA) * LOG2E); rsA += s[mt][nt][1];
                s[mt][nt][2] = fexp2((s[mt][nt][2] - mnB) * LOG2E); rsB += s[mt][nt][2];
                s[mt][nt][3] = fexp2((s[mt][nt][3] - mnB) * LOG2E); rsB += s[mt][nt][3];
            }
            rsA += __shfl_xor_sync(0xffffffffu, rsA, 1);
            rsA += __shfl_xor_sync(0xffffffffu, rsA, 2);
            rsB += __shfl_xor_sync(0xffffffffu, rsB, 1);
            rsB += __shfl_xor_sync(0xffffffffu, rsB, 2);
            mrow[mt][0] = mnA; mrow[mt][1] = mnB;
            lrow[mt][0] = lrow[mt][0] * cA + rsA;
            lrow[mt][1] = lrow[mt][1] * cB + rsB;
#pragma unroll
            for (int nt = 0; nt < 8; nt++) {
                o[mt][nt][0] *= cA; o[mt][nt][1] *= cA;
                o[mt][nt][2] *= cB; o[mt][nt][3] *= cB;
            }
            int ra = warpQ + mt * 16 + r0;
#pragma unroll
            for (int nt = 0; nt < 8; nt++) {
                int cc = nt * 8 + c0 * 2;
                Ps[ra * 68 + cc]           = to_tf32(s[mt][nt][0]);
                Ps[ra * 68 + cc + 1]       = to_tf32(s[mt][nt][1]);
                Ps[(ra + 8) * 68 + cc]     = to_tf32(s[mt][nt][2]);
                Ps[(ra + 8) * 68 + cc + 1] = to_tf32(s[mt][nt][3]);
            }
        }
        __syncwarp();

        // O += P @ V
#pragma unroll
        for (int kk = 0; kk < 8; kk++) {
            int kc = kk * 8 + c0;
            float bf[8][2];
#pragma unroll
            for (int nt = 0; nt < 8; nt++) {
                int n = nt * 8 + r0;
                bf[nt][0] = Vs[kc * 72 + n];
                bf[nt][1] = Vs[(kc + 4) * 72 + n];
            }
            float pa[2][4];
#pragma unroll
            for (int mt = 0; mt < 2; mt++) {
                int rr = warpQ + mt * 16 + r0;
                pa[mt][0] = Ps[rr * 68 + kc];
                pa[mt][1] = Ps[(rr + 8) * 68 + kc];
                pa[mt][2] = Ps[rr * 68 + kc + 4];
                pa[mt][3] = Ps[(rr + 8) * 68 + kc + 4];
            }
#pragma unroll
            for (int mt = 0; mt < 2; mt++)
#pragma unroll
                for (int nt = 0; nt < 8; nt++)
                    mma_tf32(o[mt][nt], pa[mt], bf[nt]);
        }
        __syncwarp();
    }

    // epilogue: normalize, write to g_ao [B,N,C]
#pragma unroll
    for (int mt = 0; mt < 2; mt++) {
        float iA = 1.f / lrow[mt][0], iB = 1.f / lrow[mt][1];
        int r = q0 + warpQ + mt * 16 + r0;
        size_t rowA = ((size_t)b * N_ + r) * C_ + h * HD_;
        size_t rowB = ((size_t)b * N_ + r + 8) * C_ + h * HD_;
#pragma unroll
        for (int nt = 0; nt < 8; nt++) {
            int d = nt * 8 + c0 * 2;
            g_ao[rowA + d]     = o[mt][nt][0] * iA;
            g_ao[rowA + d + 1] = o[mt][nt][1] * iA;
            g_ao[rowB + d]     = o[mt][nt][2] * iB;
            g_ao[rowB + d + 1] = o[mt][nt][3] * iB;
        }
    }
}

// ============================================================================
extern "C" void kernel_launch(void* const* d_in, const int* in_sizes, int n_in,
                              void* d_out, int out_size)
{
    const float* x     = (const float*)d_in[0];
    const float* cosT  = (const float*)d_in[1];
    const float* sinT  = (const float*)d_in[2];
    const float* Wqkv  = (const float*)d_in[3];
    const float* Wproj = (const float*)d_in[4];
    const float* bproj = (const float*)d_in[5];
    float* out = (float*)d_out;

    cudaFuncSetAttribute(gemm_tc<1>,
                         cudaFuncAttributeMaxDynamicSharedMemorySize, GEMM_SMEM_BYTES);
    cudaFuncSetAttribute(gemm_tc<0>,
                         cudaFuncAttributeMaxDynamicSharedMemorySize, GEMM_SMEM_BYTES);
    cudaFuncSetAttribute(attn_kernel,
                         cudaFuncAttributeMaxDynamicSharedMemorySize, ATTN_SMEM_BYTES);

    // 1) QKV GEMM + RoPE -> g_q/g_k/g_v  (M=8192, Nd=3072, K=1024)
    dim3 g1(3 * C_ / 256, (B_ * N_) / 128);
    gemm_tc<1><<<g1, 256, GEMM_SMEM_BYTES>>>(x, Wqkv, nullptr, cosT, sinT, nullptr);

    // 2) flash attention -> g_ao
    dim3 g2(N_ / 128, BH_);
    attn_kernel<<<g2, 128, ATTN_SMEM_BYTES>>>();

    // 3) out proj + bias -> out  (M=8192, Nd=1024, K=1024)
    dim3 g3(C_ / 256, (B_ * N_) / 128);
    gemm_tc<0><<<g3, 256, GEMM_SMEM_BYTES>>>(nullptr, Wproj, bproj, nullptr, nullptr, out);
}